// round 16
// baseline (speedup 1.0000x reference)
#include <cuda_runtime.h>
#include <cuda_fp16.h>
#include <stdint.h>

#define N_POINTS 262144
#define SP_FEAT  128
#define HIDDEN   64
#define EMBED    256
#define NUM_SP   4096
#define NUM_SP2  256
#define PAD_LIMIT 64
#define SUB_M    32
#define NSUB     (N_POINTS / SUB_M)    // 8192
#define GRID_MAIN 148
#define NQUAD    6

// ---------------- device scratch ----------------
__device__ int g_tok[NUM_SP * EMBED];          // float bits, values >= 0
__device__ int g_mask_is_i32;
__device__ int g_work;                         // work queue head (reset by k_prep_w)
// prepacked fp16 B fragments (mma.m16n8k16), uint2 = {reg0, reg1}
__device__ __align__(16) uint2 g_w1f[8 * 8 * 32];    // [n8][ks][lane] (16 KB)
__device__ __align__(16) uint2 g_w2f[32 * 4 * 32];   // [n8][ks][lane] (32 KB)

// ---------------- helpers ----------------
__device__ __forceinline__ uint32_t smem_u32(const void* p) {
    uint32_t a;
    asm("{ .reg .u64 t; cvta.to.shared.u64 t, %1; cvt.u32.u64 %0, t; }" : "=r"(a) : "l"(p));
    return a;
}
__device__ __forceinline__ uint32_t off256(uint32_t row, uint32_t k) {
    return row * 256u + (((k >> 3) ^ (row & 7u)) << 4) + (k & 7u) * 2u;
}
__device__ __forceinline__ uint32_t off128(uint32_t row, uint32_t k) {
    return row * 128u + ((((k >> 3) ^ (row & 7u)) & 7u) << 4) + (k & 7u) * 2u;
}
__device__ __forceinline__ uint32_t pack_hf2(float a, float b) {
    __half2 t = __floats2half2_rn(a, b);       // .x=a (low half)
    return *(uint32_t*)&t;
}
__device__ __forceinline__ void ldsm4(uint32_t r[4], uint32_t addr) {
    asm volatile("ldmatrix.sync.aligned.m8n8.x4.shared.b16 {%0,%1,%2,%3}, [%4];"
                 : "=r"(r[0]), "=r"(r[1]), "=r"(r[2]), "=r"(r[3]) : "r"(addr));
}
__device__ __forceinline__ uint2 lds64(uint32_t addr) {
    uint2 r;
    asm volatile("ld.shared.v2.b32 {%0,%1}, [%2];" : "=r"(r.x), "=r"(r.y) : "r"(addr));
    return r;
}
__device__ __forceinline__ void mma_f16(float c[4], const uint32_t a[4],
                                        uint32_t b0, uint32_t b1) {
    asm volatile("mma.sync.aligned.m16n8k16.row.col.f32.f16.f16.f32 "
                 "{%0,%1,%2,%3}, {%4,%5,%6,%7}, {%8,%9}, {%0,%1,%2,%3};"
                 : "+f"(c[0]), "+f"(c[1]), "+f"(c[2]), "+f"(c[3])
                 : "r"(a[0]), "r"(a[1]), "r"(a[2]), "r"(a[3]), "r"(b0), "r"(b1));
}
__device__ __forceinline__ void cp_async16(uint32_t dst, const void* src) {
    asm volatile("cp.async.cg.shared.global [%0], [%1], 16;" :: "r"(dst), "l"(src));
}
#define CP_COMMIT() asm volatile("cp.async.commit_group;" ::: "memory")
#define CP_WAIT0()  asm volatile("cp.async.wait_group 0;"  ::: "memory")
#define QBAR(id) asm volatile("bar.sync %0, 128;" :: "r"(id) : "memory")

// ---------------- smem layout ----------------
// per quad (28672 B): XF 8192 (32x128 fp16) | HF 4096 (32x64 fp16) | STG 16384 (32x128 f32)
#define Q_XF    0
#define Q_HF    8192
#define Q_STG   12288
#define QUAD_SZ 28672
#define S_W1F   (NQUAD * QUAD_SZ)      // 172032, 16384 B
#define S_W2F   (S_W1F + 16384)        // 188416, 32768 B
#define S_B1    (S_W2F + 32768)        // 221184, 64 f32
#define S_B2    (S_B1 + 256)           // 256 f32
#define S_IDX   (S_B2 + 1024)          // 6 quads x 2 ints
#define SMEM_TOTAL (S_IDX + 64)        // 222528

// ---------------- prep kernel ----------------
__global__ void k_prep_w(const float* __restrict__ W1, const float* __restrict__ W2,
                         const int* __restrict__ msk) {
    int i = blockIdx.x * blockDim.x + threadIdx.x;     // 8192 threads
    if (blockIdx.x == 0) {
        __shared__ int bad;
        if (threadIdx.x == 0) { bad = 0; g_work = 0; }
        __syncthreads();
        for (int j = threadIdx.x; j < 1024; j += blockDim.x)
            if ((unsigned)msk[j] > 1u) atomicOr(&bad, 1);
        __syncthreads();
        if (threadIdx.x == 0) g_mask_is_i32 = bad ? 0 : 1;
    }
    if (i < 2048) {                                     // layer1: [n8(8)][ks(8)][lane]
        int lane = i & 31, ks = (i >> 5) & 7, n8 = i >> 8;
        int n  = 8 * n8 + (lane >> 2);
        int k0 = 16 * ks + 2 * (lane & 3);
        uint2 f;
        f.x = pack_hf2(W1[k0 * HIDDEN + n],       W1[(k0 + 1) * HIDDEN + n]);
        f.y = pack_hf2(W1[(k0 + 8) * HIDDEN + n], W1[(k0 + 9) * HIDDEN + n]);
        g_w1f[i] = f;
    } else if (i < 2048 + 4096) {                       // layer2: [n8(32)][ks(4)][lane]
        int j = i - 2048;
        int lane = j & 31, ks = (j >> 5) & 3, n8 = j >> 7;
        int n  = 8 * n8 + (lane >> 2);
        int k0 = 16 * ks + 2 * (lane & 3);
        uint2 f;
        f.x = pack_hf2(W2[k0 * EMBED + n],       W2[(k0 + 1) * EMBED + n]);
        f.y = pack_hf2(W2[(k0 + 8) * EMBED + n], W2[(k0 + 9) * EMBED + n]);
        g_w2f[j] = f;
    }
}

// ---------------- persistent main kernel: 6 quad pipelines, x double-buffered ----------------
__global__ __launch_bounds__(768, 1)
void k_main(const float* __restrict__ x, const int* __restrict__ idx10,
            const float* __restrict__ b1, const float* __restrict__ b2)
{
    extern __shared__ char sm[];
    const uint32_t smb = smem_u32(sm);
    const int tid  = threadIdx.x;
    const int wid  = tid >> 5;
    const int lane = tid & 31;
    const int qid  = wid >> 2;        // quad 0..5
    const int wq   = wid & 3;
    const int tiq  = tid & 127;       // thread-in-quad
    const int q    = lane & 3;
    const int rb   = lane >> 2;
    const int arow  = lane & 15;
    const int acol8 = (lane >> 4) * 8;
    const int barid = qid + 1;

    const uint32_t qb = smb + (uint32_t)qid * QUAD_SZ;
    int (*s_idx)[2] = (int(*)[2])(sm + S_IDX);

    // copy B-fragment tables into smem (48 KB, L2-hot)
    {
        uint4*       d1 = (uint4*)(sm + S_W1F);
        const uint4* s1 = (const uint4*)g_w1f;
        for (int i = tid; i < 1024; i += 768) d1[i] = s1[i];
        uint4*       d2 = (uint4*)(sm + S_W2F);
        const uint4* s2 = (const uint4*)g_w2f;
        for (int i = tid; i < 2048; i += 768) d2[i] = s2[i];
    }
    if (tid < 64)  ((float*)(sm + S_B1))[tid] = b1[tid];
    if (tid < 256) ((float*)(sm + S_B2))[tid] = b2[tid];
    if (tiq == 0)  s_idx[qid][0] = atomicAdd(&g_work, 1);
    __syncthreads();   // tables + biases + slot0 visible

    const uint32_t w1b = smb + S_W1F;
    const uint32_t w2b = smb + S_W2F;

    int my = s_idx[qid][0];
    // prefetch stage(my)
    if (my < NSUB) {
        #pragma unroll
        for (int j = 0; j < 8; j++) {
            int i = tiq + j * 128;
            cp_async16(qb + Q_STG + i * 16,
                       ((const float4*)x) + (size_t)(my * SUB_M + (i >> 5)) * 32 + (i & 31));
        }
    }
    CP_COMMIT();
    if (tiq == 0) s_idx[qid][1] = atomicAdd(&g_work, 1);
    int par = 0;

    while (my < NSUB) {
        // ---- convert own staged rows -> XF (fp16) ----
        CP_WAIT0();
        #pragma unroll
        for (int j = 0; j < 8; j++) {
            int i = tiq + j * 128;
            int p = i >> 5, c4 = i & 31;
            float4 v = ((const float4*)(sm + (qid * QUAD_SZ + Q_STG)))[i];
            uint2 hf = make_uint2(pack_hf2(v.x, v.y), pack_hf2(v.z, v.w));
            *(uint2*)(sm + qid * QUAD_SZ + Q_XF + off256((uint32_t)p, (uint32_t)(c4 * 4))) = hf;
        }
        QBAR(barid);                              // XF ready; slot (par^1) visible

        const int nxt = s_idx[qid][par ^ 1];
        if (nxt < NSUB) {                         // prefetch next subtile into stage
            #pragma unroll
            for (int j = 0; j < 8; j++) {
                int i = tiq + j * 128;
                cp_async16(qb + Q_STG + i * 16,
                           ((const float4*)x) + (size_t)(nxt * SUB_M + (i >> 5)) * 32 + (i & 31));
            }
        }
        CP_COMMIT();
        if (tiq == 0 && nxt < NSUB) s_idx[qid][par] = atomicAdd(&g_work, 1);

        // ================= layer 1: 32 rows (mt 0,1), cols 16wq..+15 =================
        float acc[2][2][4];   // [mt][nth][4]
        #pragma unroll
        for (int mt = 0; mt < 2; mt++)
            #pragma unroll
            for (int nth = 0; nth < 2; nth++)
                #pragma unroll
                for (int j = 0; j < 4; j++) acc[mt][nth][j] = 0.f;

        {
            uint32_t af[2][2][4];   // [buf][mt]
            #pragma unroll
            for (int mt = 0; mt < 2; mt++) {
                uint32_t o = off256((uint32_t)(16*mt + arow), (uint32_t)acol8);
                ldsm4(af[0][mt], qb + Q_XF + o);
            }
            #pragma unroll
            for (int ks = 0; ks < 8; ks++) {
                const int cur = ks & 1;
                if (ks < 7) {
                    #pragma unroll
                    for (int mt = 0; mt < 2; mt++) {
                        uint32_t o = off256((uint32_t)(16*mt + arow),
                                            (uint32_t)(16*(ks + 1) + acol8));
                        ldsm4(af[cur ^ 1][mt], qb + Q_XF + o);
                    }
                }
                #pragma unroll
                for (int nth = 0; nth < 2; nth++) {
                    const uint2 f = lds64(w1b + (((2*wq + nth)*8 + ks)*32 + lane) * 8);
                    #pragma unroll
                    for (int mt = 0; mt < 2; mt++)
                        mma_f16(acc[mt][nth], af[cur][mt], f.x, f.y);
                }
            }
        }

        // epilogue 1: bias + relu -> fp16 into quad HF
        {
            const float* b1s = (const float*)(sm + S_B1);
            #pragma unroll
            for (int nth = 0; nth < 2; nth++) {
                const int col = 16*wq + 8*nth + 2*q;
                const float bia0 = b1s[col], bia1 = b1s[col + 1];
                #pragma unroll
                for (int mt = 0; mt < 2; mt++) {
                    int r1 = 16*mt + rb, r2 = r1 + 8;
                    float v00 = fmaxf(acc[mt][nth][0] + bia0, 0.f);
                    float v01 = fmaxf(acc[mt][nth][1] + bia1, 0.f);
                    float v10 = fmaxf(acc[mt][nth][2] + bia0, 0.f);
                    float v11 = fmaxf(acc[mt][nth][3] + bia1, 0.f);
                    *(uint32_t*)(sm + qid * QUAD_SZ + Q_HF + off128((uint32_t)r1, (uint32_t)col))
                        = pack_hf2(v00, v01);
                    *(uint32_t*)(sm + qid * QUAD_SZ + Q_HF + off128((uint32_t)r2, (uint32_t)col))
                        = pack_hf2(v10, v11);
                }
            }
        }
        QBAR(barid);                              // HF ready

        // sp ids for this thread's fragment rows
        int sp0[2], sp1[2];
        #pragma unroll
        for (int mt = 0; mt < 2; mt++) {
            sp0[mt] = idx10[my * SUB_M + 16*mt + rb];
            sp1[mt] = idx10[my * SUB_M + 16*mt + rb + 8];
        }

        // ================= layer 2: 32 rows, cols 64wq..+63, two 32-col passes =================
        const float* b2s = (const float*)(sm + S_B2);
        #pragma unroll 1
        for (int hf = 0; hf < 2; hf++) {
            float a2[4][2][4];   // [ntl][mt][4] = 32 regs
            #pragma unroll
            for (int ntl = 0; ntl < 4; ntl++)
                #pragma unroll
                for (int mt = 0; mt < 2; mt++)
                    #pragma unroll
                    for (int j = 0; j < 4; j++) a2[ntl][mt][j] = 0.f;

            {
                uint32_t af[2][2][4];   // [buf][mt]
                #pragma unroll
                for (int mt = 0; mt < 2; mt++) {
                    uint32_t o = off128((uint32_t)(16*mt + arow), (uint32_t)acol8);
                    ldsm4(af[0][mt], qb + Q_HF + o);
                }
                #pragma unroll
                for (int ks = 0; ks < 4; ks++) {
                    const int cur = ks & 1;
                    if (ks < 3) {
                        #pragma unroll
                        for (int mt = 0; mt < 2; mt++) {
                            uint32_t o = off128((uint32_t)(16*mt + arow),
                                                (uint32_t)(16*(ks + 1) + acol8));
                            ldsm4(af[cur ^ 1][mt], qb + Q_HF + o);
                        }
                    }
                    #pragma unroll
                    for (int ntl = 0; ntl < 4; ntl++) {
                        const uint2 f = lds64(w2b + (((8*wq + 4*hf + ntl)*4 + ks)*32 + lane) * 8);
                        #pragma unroll
                        for (int mt = 0; mt < 2; mt++)
                            mma_f16(a2[ntl][mt], af[cur][mt], f.x, f.y);
                    }
                }
            }

            // epilogue 2: bias + relu + 2-row segmented max -> atomicMax
            #pragma unroll
            for (int ntl = 0; ntl < 4; ntl++) {
                int colb = 64*wq + 8*(4*hf + ntl) + 2*q;
                #pragma unroll
                for (int c01 = 0; c01 < 2; c01++) {
                    int col = colb + c01;
                    float bias = b2s[col];
                    #pragma unroll
                    for (int mt = 0; mt < 2; mt++) {
                        float v0 = fmaxf(a2[ntl][mt][c01]     + bias, 0.f);
                        float v1 = fmaxf(a2[ntl][mt][c01 + 2] + bias, 0.f);
                        if (sp0[mt] == sp1[mt]) {
                            atomicMax(&g_tok[sp0[mt] * EMBED + col],
                                      __float_as_int(fmaxf(v0, v1)));
                        } else {
                            atomicMax(&g_tok[sp0[mt] * EMBED + col], __float_as_int(v0));
                            atomicMax(&g_tok[sp1[mt] * EMBED + col], __float_as_int(v1));
                        }
                    }
                }
            }
        }

        my = nxt;
        par ^= 1;
    }
}

// ---------------- scatter: 8 sps per 512-thread block ----------------
__global__ void k_scatter(const int* __restrict__ idx21,
                          const void* __restrict__ is_masked,
                          float* __restrict__ out)
{
    const int grp = threadIdx.x >> 6;               // 0..7
    const int t64 = threadIdx.x & 63;
    const int sp  = blockIdx.x * 8 + grp;
    __shared__ int s_off[8];

    if (t64 == 0) {
        const int mode = g_mask_is_i32;
        const int* mi = (const int*)is_masked;
        const unsigned char* mb = (const unsigned char*)is_masked;
        int g = idx21[sp];
        int lo = 0, hi = sp;
        while (lo < hi) { int mid = (lo + hi) >> 1; if (idx21[mid] < g) lo = mid + 1; else hi = mid; }
        bool me = mode ? (mi[sp] != 0) : (mb[sp] != 0);
        int rank = 0;
        for (int j = lo; j < sp; j++) {
            bool fj = mode ? (mi[j] != 0) : (mb[j] != 0);
            rank += (fj == me);
        }
        int b = me ? (NUM_SP2 * PAD_LIMIT * EMBED) : 0;
        s_off[grp] = b + (g * PAD_LIMIT + rank) * EMBED;
    }
    __syncthreads();
    float4*       dst = (float4*)(out + s_off[grp]);
    const float4* src = (const float4*)((const float*)g_tok + sp * EMBED);
    dst[t64] = src[t64];
}

// ---------------- launch ----------------
extern "C" void kernel_launch(void* const* d_in, const int* in_sizes, int n_in,
                              void* d_out, int out_size) {
    const float* x     = (const float*)d_in[0];
    const int*   idx10 = (const int*)d_in[1];
    const int*   idx21 = (const int*)d_in[2];
    const void*  msk   = (const void*)d_in[3];
    const float* W1    = (const float*)d_in[4];
    const float* b1    = (const float*)d_in[5];
    const float* W2    = (const float*)d_in[6];
    const float* b2    = (const float*)d_in[7];
    float* out = (float*)d_out;

    cudaFuncSetAttribute(k_main, cudaFuncAttributeMaxDynamicSharedMemorySize, SMEM_TOTAL);

    void* tok_ptr = nullptr;
    cudaGetSymbolAddress(&tok_ptr, g_tok);

    cudaMemsetAsync(out, 0, (size_t)out_size * sizeof(float));
    cudaMemsetAsync(tok_ptr, 0, (size_t)NUM_SP * EMBED * sizeof(int));
    k_prep_w<<<32, 256>>>(W1, W2, (const int*)msk);
    k_main<<<GRID_MAIN, 768, SMEM_TOTAL>>>(x, idx10, b1, b2);
    k_scatter<<<NUM_SP / 8, 512>>>(idx21, msk, out);
}

// round 17
// speedup vs baseline: 1.0732x; 1.0732x over previous
#include <cuda_runtime.h>
#include <cuda_fp16.h>
#include <stdint.h>

#define N_POINTS 262144
#define SP_FEAT  128
#define HIDDEN   64
#define EMBED    256
#define NUM_SP   4096
#define NUM_SP2  256
#define PAD_LIMIT 64
#define SUB_M    32
#define NSUB     (N_POINTS / SUB_M)    // 8192
#define GRID_MAIN 148
#define NQUAD    6

// ---------------- device scratch ----------------
__device__ int g_tok[NUM_SP * EMBED];          // float bits, values >= 0
__device__ int g_mask_is_i32;
__device__ int g_work;                         // work queue head (reset by k_prep)
// prepacked fp16 B fragments (mma.m16n8k16), uint2 = {reg0, reg1}
__device__ __align__(16) uint2 g_w1f[8 * 8 * 32];    // [n8][ks][lane] (16 KB)
__device__ __align__(16) uint2 g_w2f[32 * 4 * 32];   // [n8][ks][lane] (32 KB)

// ---------------- helpers ----------------
__device__ __forceinline__ uint32_t smem_u32(const void* p) {
    uint32_t a;
    asm("{ .reg .u64 t; cvta.to.shared.u64 t, %1; cvt.u32.u64 %0, t; }" : "=r"(a) : "l"(p));
    return a;
}
__device__ __forceinline__ uint32_t off256(uint32_t row, uint32_t k) {
    return row * 256u + (((k >> 3) ^ (row & 7u)) << 4) + (k & 7u) * 2u;
}
__device__ __forceinline__ uint32_t off128(uint32_t row, uint32_t k) {
    return row * 128u + ((((k >> 3) ^ (row & 7u)) & 7u) << 4) + (k & 7u) * 2u;
}
__device__ __forceinline__ uint32_t pack_hf2(float a, float b) {
    __half2 t = __floats2half2_rn(a, b);       // .x=a (low half)
    return *(uint32_t*)&t;
}
__device__ __forceinline__ void ldsm4(uint32_t r[4], uint32_t addr) {
    asm volatile("ldmatrix.sync.aligned.m8n8.x4.shared.b16 {%0,%1,%2,%3}, [%4];"
                 : "=r"(r[0]), "=r"(r[1]), "=r"(r[2]), "=r"(r[3]) : "r"(addr));
}
__device__ __forceinline__ uint2 lds64(uint32_t addr) {
    uint2 r;
    asm volatile("ld.shared.v2.b32 {%0,%1}, [%2];" : "=r"(r.x), "=r"(r.y) : "r"(addr));
    return r;
}
__device__ __forceinline__ void mma_f16(float c[4], const uint32_t a[4],
                                        uint32_t b0, uint32_t b1) {
    asm volatile("mma.sync.aligned.m16n8k16.row.col.f32.f16.f16.f32 "
                 "{%0,%1,%2,%3}, {%4,%5,%6,%7}, {%8,%9}, {%0,%1,%2,%3};"
                 : "+f"(c[0]), "+f"(c[1]), "+f"(c[2]), "+f"(c[3])
                 : "r"(a[0]), "r"(a[1]), "r"(a[2]), "r"(a[3]), "r"(b0), "r"(b1));
}
#define QBAR(id) asm volatile("bar.sync %0, 128;" :: "r"(id) : "memory")

// ---------------- smem layout ----------------
// per quad (12288 B): XF 8192 (32x128 fp16) | HF 4096 (32x64 fp16)
#define Q_XF    0
#define Q_HF    8192
#define QUAD_SZ 12288
#define S_W1F   (NQUAD * QUAD_SZ)      // 73728, 16384 B
#define S_W2F   (S_W1F + 16384)        // 90112, 32768 B
#define S_B1    (S_W2F + 32768)        // 122880, 64 f32
#define S_B2    (S_B1 + 256)           // 256 f32
#define S_IDX   (S_B2 + 1024)          // 6 quads x 2 ints
#define SMEM_TOTAL (S_IDX + 64)        // 124224

// ---------------- prep kernel: pack W frags, detect mask dtype, zero g_tok, reset queue ----------------
__global__ void k_prep(const float* __restrict__ W1, const float* __restrict__ W2,
                       const int* __restrict__ msk) {
    int i = blockIdx.x * blockDim.x + threadIdx.x;     // 8192 threads
    if (blockIdx.x == 0) {
        __shared__ int bad;
        if (threadIdx.x == 0) { bad = 0; g_work = 0; }
        __syncthreads();
        for (int j = threadIdx.x; j < 1024; j += blockDim.x)
            if ((unsigned)msk[j] > 1u) atomicOr(&bad, 1);
        __syncthreads();
        if (threadIdx.x == 0) g_mask_is_i32 = bad ? 0 : 1;
    }
    // zero g_tok (1M ints): 32 uint4 per thread
    {
        uint4* t4 = (uint4*)g_tok;
        const uint4 z = make_uint4(0, 0, 0, 0);
        for (int j = i; j < NUM_SP * EMBED / 4; j += 8192) t4[j] = z;
    }
    if (i < 2048) {                                     // layer1: [n8(8)][ks(8)][lane]
        int lane = i & 31, ks = (i >> 5) & 7, n8 = i >> 8;
        int n  = 8 * n8 + (lane >> 2);
        int k0 = 16 * ks + 2 * (lane & 3);
        uint2 f;
        f.x = pack_hf2(W1[k0 * HIDDEN + n],       W1[(k0 + 1) * HIDDEN + n]);
        f.y = pack_hf2(W1[(k0 + 8) * HIDDEN + n], W1[(k0 + 9) * HIDDEN + n]);
        g_w1f[i] = f;
    } else if (i < 2048 + 4096) {                       // layer2: [n8(32)][ks(4)][lane]
        int j = i - 2048;
        int lane = j & 31, ks = (j >> 5) & 3, n8 = j >> 7;
        int n  = 8 * n8 + (lane >> 2);
        int k0 = 16 * ks + 2 * (lane & 3);
        uint2 f;
        f.x = pack_hf2(W2[k0 * EMBED + n],       W2[(k0 + 1) * EMBED + n]);
        f.y = pack_hf2(W2[(k0 + 8) * EMBED + n], W2[(k0 + 9) * EMBED + n]);
        g_w2f[j] = f;
    }
}

// ---------------- zero the output buffer (replaces cudaMemsetAsync) ----------------
__global__ void k_zero_out(float* __restrict__ out, int n4) {
    const uint4 z = make_uint4(0, 0, 0, 0);
    for (int i = blockIdx.x * blockDim.x + threadIdx.x; i < n4; i += gridDim.x * blockDim.x)
        ((uint4*)out)[i] = z;
}

// ---------------- persistent main kernel: 6 independent 4-warp quad pipelines ----------------
__global__ __launch_bounds__(768, 1)
void k_main(const float* __restrict__ x, const int* __restrict__ idx10,
            const float* __restrict__ b1, const float* __restrict__ b2)
{
    extern __shared__ char sm[];
    const uint32_t smb = smem_u32(sm);
    const int tid  = threadIdx.x;
    const int wid  = tid >> 5;
    const int lane = tid & 31;
    const int qid  = wid >> 2;        // quad 0..5
    const int wq   = wid & 3;
    const int tiq  = tid & 127;       // thread-in-quad
    const int q    = lane & 3;
    const int rb   = lane >> 2;
    const int arow  = lane & 15;
    const int acol8 = (lane >> 4) * 8;
    const int barid = qid + 1;

    const uint32_t qb = smb + (uint32_t)qid * QUAD_SZ;
    int (*s_idx)[2] = (int(*)[2])(sm + S_IDX);

    // copy B-fragment tables into smem (48 KB, L2-hot; immune to x-stream eviction)
    {
        uint4*       d1 = (uint4*)(sm + S_W1F);
        const uint4* s1 = (const uint4*)g_w1f;
        for (int i = tid; i < 1024; i += 768) d1[i] = s1[i];
        uint4*       d2 = (uint4*)(sm + S_W2F);
        const uint4* s2 = (const uint4*)g_w2f;
        for (int i = tid; i < 2048; i += 768) d2[i] = s2[i];
    }
    if (tid < 64)  ((float*)(sm + S_B1))[tid] = b1[tid];
    if (tid < 256) ((float*)(sm + S_B2))[tid] = b2[tid];
    if (tiq == 0) {
        s_idx[qid][0] = atomicAdd(&g_work, 1);
        s_idx[qid][1] = atomicAdd(&g_work, 1);
    }
    __syncthreads();   // tables + biases + both index slots visible

    const uint32_t w1b = smb + S_W1F;
    const uint32_t w2b = smb + S_W2F;

    int par = 0;
    for (;;) {
        const int my = s_idx[qid][par];
        if (my >= NSUB) break;

        // ---- load own 32 rows of x (streaming LDG, MLP=8), fp16 round -> XF ----
        {
            float4 v[8];
            #pragma unroll
            for (int j = 0; j < 8; j++) {
                int i = tiq + j * 128;
                v[j] = __ldcs(((const float4*)x) +
                              (size_t)(my * SUB_M + (i >> 5)) * 32 + (i & 31));
            }
            #pragma unroll
            for (int j = 0; j < 8; j++) {
                int i = tiq + j * 128;
                int p = i >> 5, c4 = i & 31;
                uint2 hf = make_uint2(pack_hf2(v[j].x, v[j].y), pack_hf2(v[j].z, v[j].w));
                uint32_t off = off256((uint32_t)p, (uint32_t)(c4 * 4));
                *(uint2*)(sm + qid * QUAD_SZ + Q_XF + off) = hf;
            }
        }
        QBAR(barid);                              // XF ready; everyone has read slot[par]

        // refill the slot just consumed (read again two iterations from now)
        if (tiq == 0) s_idx[qid][par] = atomicAdd(&g_work, 1);

        // ================= layer 1: 32 rows (mt 0,1), cols 16wq..+15 =================
        float acc[2][2][4];   // [mt][nth][4]
        #pragma unroll
        for (int mt = 0; mt < 2; mt++)
            #pragma unroll
            for (int nth = 0; nth < 2; nth++)
                #pragma unroll
                for (int j = 0; j < 4; j++) acc[mt][nth][j] = 0.f;

        {
            uint32_t af[2][2][4];   // [buf][mt]
            #pragma unroll
            for (int mt = 0; mt < 2; mt++) {
                uint32_t o = off256((uint32_t)(16*mt + arow), (uint32_t)acol8);
                ldsm4(af[0][mt], qb + Q_XF + o);
            }
            #pragma unroll
            for (int ks = 0; ks < 8; ks++) {
                const int cur = ks & 1;
                if (ks < 7) {
                    #pragma unroll
                    for (int mt = 0; mt < 2; mt++) {
                        uint32_t o = off256((uint32_t)(16*mt + arow),
                                            (uint32_t)(16*(ks + 1) + acol8));
                        ldsm4(af[cur ^ 1][mt], qb + Q_XF + o);
                    }
                }
                #pragma unroll
                for (int nth = 0; nth < 2; nth++) {
                    const uint2 f = lds64(w1b + (((2*wq + nth)*8 + ks)*32 + lane) * 8);
                    #pragma unroll
                    for (int mt = 0; mt < 2; mt++)
                        mma_f16(acc[mt][nth], af[cur][mt], f.x, f.y);
                }
            }
        }

        // epilogue 1: bias + relu -> fp16 into quad HF
        {
            const float* b1s = (const float*)(sm + S_B1);
            #pragma unroll
            for (int nth = 0; nth < 2; nth++) {
                const int col = 16*wq + 8*nth + 2*q;
                const float bia0 = b1s[col], bia1 = b1s[col + 1];
                #pragma unroll
                for (int mt = 0; mt < 2; mt++) {
                    int r1 = 16*mt + rb, r2 = r1 + 8;
                    float v00 = fmaxf(acc[mt][nth][0] + bia0, 0.f);
                    float v01 = fmaxf(acc[mt][nth][1] + bia1, 0.f);
                    float v10 = fmaxf(acc[mt][nth][2] + bia0, 0.f);
                    float v11 = fmaxf(acc[mt][nth][3] + bia1, 0.f);
                    *(uint32_t*)(sm + qid * QUAD_SZ + Q_HF + off128((uint32_t)r1, (uint32_t)col))
                        = pack_hf2(v00, v01);
                    *(uint32_t*)(sm + qid * QUAD_SZ + Q_HF + off128((uint32_t)r2, (uint32_t)col))
                        = pack_hf2(v10, v11);
                }
            }
        }
        QBAR(barid);                              // HF ready; slot refill visible next iter

        // sp ids for this thread's fragment rows
        int sp0[2], sp1[2];
        #pragma unroll
        for (int mt = 0; mt < 2; mt++) {
            sp0[mt] = idx10[my * SUB_M + 16*mt + rb];
            sp1[mt] = idx10[my * SUB_M + 16*mt + rb + 8];
        }

        // ================= layer 2: 32 rows, cols 64wq..+63, two 32-col passes =================
        const float* b2s = (const float*)(sm + S_B2);
        #pragma unroll 1
        for (int hf = 0; hf < 2; hf++) {
            float a2[4][2][4];   // [ntl][mt][4] = 32 regs
            #pragma unroll
            for (int ntl = 0; ntl < 4; ntl++)
                #pragma unroll
                for (int mt = 0; mt < 2; mt++)
                    #pragma unroll
                    for (int j = 0; j < 4; j++) a2[ntl][mt][j] = 0.f;

            {
                uint32_t af[2][2][4];   // [buf][mt]
                #pragma unroll
                for (int mt = 0; mt < 2; mt++) {
                    uint32_t o = off128((uint32_t)(16*mt + arow), (uint32_t)acol8);
                    ldsm4(af[0][mt], qb + Q_HF + o);
                }
                #pragma unroll
                for (int ks = 0; ks < 4; ks++) {
                    const int cur = ks & 1;
                    if (ks < 3) {
                        #pragma unroll
                        for (int mt = 0; mt < 2; mt++) {
                            uint32_t o = off128((uint32_t)(16*mt + arow),
                                                (uint32_t)(16*(ks + 1) + acol8));
                            ldsm4(af[cur ^ 1][mt], qb + Q_HF + o);
                        }
                    }
                    #pragma unroll
                    for (int ntl = 0; ntl < 4; ntl++) {
                        const uint2 f = lds64(w2b + (((8*wq + 4*hf + ntl)*4 + ks)*32 + lane) * 8);
                        #pragma unroll
                        for (int mt = 0; mt < 2; mt++)
                            mma_f16(a2[ntl][mt], af[cur][mt], f.x, f.y);
                    }
                }
            }

            // epilogue 2: bias + relu + 2-row segmented max -> atomicMax
            #pragma unroll
            for (int ntl = 0; ntl < 4; ntl++) {
                int colb = 64*wq + 8*(4*hf + ntl) + 2*q;
                #pragma unroll
                for (int c01 = 0; c01 < 2; c01++) {
                    int col = colb + c01;
                    float bias = b2s[col];
                    #pragma unroll
                    for (int mt = 0; mt < 2; mt++) {
                        float v0 = fmaxf(a2[ntl][mt][c01]     + bias, 0.f);
                        float v1 = fmaxf(a2[ntl][mt][c01 + 2] + bias, 0.f);
                        if (sp0[mt] == sp1[mt]) {
                            atomicMax(&g_tok[sp0[mt] * EMBED + col],
                                      __float_as_int(fmaxf(v0, v1)));
                        } else {
                            atomicMax(&g_tok[sp0[mt] * EMBED + col], __float_as_int(v0));
                            atomicMax(&g_tok[sp1[mt] * EMBED + col], __float_as_int(v1));
                        }
                    }
                }
            }
        }

        par ^= 1;
    }
}

// ---------------- scatter: 8 sps per 512-thread block ----------------
__global__ void k_scatter(const int* __restrict__ idx21,
                          const void* __restrict__ is_masked,
                          float* __restrict__ out)
{
    const int grp = threadIdx.x >> 6;               // 0..7
    const int t64 = threadIdx.x & 63;
    const int sp  = blockIdx.x * 8 + grp;
    __shared__ int s_off[8];

    if (t64 == 0) {
        const int mode = g_mask_is_i32;
        const int* mi = (const int*)is_masked;
        const unsigned char* mb = (const unsigned char*)is_masked;
        int g = idx21[sp];
        int lo = 0, hi = sp;
        while (lo < hi) { int mid = (lo + hi) >> 1; if (idx21[mid] < g) lo = mid + 1; else hi = mid; }
        bool me = mode ? (mi[sp] != 0) : (mb[sp] != 0);
        int rank = 0;
        for (int j = lo; j < sp; j++) {
            bool fj = mode ? (mi[j] != 0) : (mb[j] != 0);
            rank += (fj == me);
        }
        int b = me ? (NUM_SP2 * PAD_LIMIT * EMBED) : 0;
        s_off[grp] = b + (g * PAD_LIMIT + rank) * EMBED;
    }
    __syncthreads();
    float4*       dst = (float4*)(out + s_off[grp]);
    const float4* src = (const float4*)((const float*)g_tok + sp * EMBED);
    dst[t64] = src[t64];
}

// ---------------- launch ----------------
extern "C" void kernel_launch(void* const* d_in, const int* in_sizes, int n_in,
                              void* d_out, int out_size) {
    const float* x     = (const float*)d_in[0];
    const int*   idx10 = (const int*)d_in[1];
    const int*   idx21 = (const int*)d_in[2];
    const void*  msk   = (const void*)d_in[3];
    const float* W1    = (const float*)d_in[4];
    const float* b1    = (const float*)d_in[5];
    const float* W2    = (const float*)d_in[6];
    const float* b2    = (const float*)d_in[7];
    float* out = (float*)d_out;

    cudaFuncSetAttribute(k_main, cudaFuncAttributeMaxDynamicSharedMemorySize, SMEM_TOTAL);

    // 4 kernels per replay: [prep, main, zero_out, scatter]
    // (ncu -s 5 -c 1 then lands on k_main of replay 2)
    k_prep<<<32, 256>>>(W1, W2, (const int*)msk);
    k_main<<<GRID_MAIN, 768, SMEM_TOTAL>>>(x, idx10, b1, b2);
    k_zero_out<<<2048, 256>>>(out, out_size / 4);
    k_scatter<<<NUM_SP / 8, 512>>>(idx21, msk, out);
}